// round 9
// baseline (speedup 1.0000x reference)
#include <cuda_runtime.h>
#include <cuda_fp16.h>
#include <cstdint>
#include <math.h>
#include <mma.h>

using namespace nvcuda;

#define DIM 128

// ---------------- scratch (device globals; zero-initialized at load) ----------------
__device__ int    g_deg [600000];    // 8 segs; restored to 0 by gather_out each run
__device__ float  g_norm[600000];
__device__ int    g_base  [300000];  // CSR row starts: [dd | gd | dg | gg] (by dst)
__device__ int    g_cursor[300000];
__device__ int    g_bsum  [512];
__device__ int    g_ebuf  [2400000];
__device__ __half g_hD[100000ull * 256];  // drug proj: cols 0-127 = dd, 128-255 = dg
__device__ __half g_hG[ 50000ull * 256];  // gene proj: cols 0-127 = gd, 128-255 = gg

// ---------------- degree counting (all 4 etypes) ----------------
__global__ void deg_all(const int* __restrict__ s0, const int* __restrict__ d0, int o0s, int o0d,
                        const int* __restrict__ s1, const int* __restrict__ d1, int o1s, int o1d,
                        const int* __restrict__ s2, const int* __restrict__ d2, int o2s, int o2d,
                        const int* __restrict__ s3, const int* __restrict__ d3, int o3s, int o3d,
                        int E) {
    int i = blockIdx.x * blockDim.x + threadIdx.x;
    const int *s, *d; int os, od, j;
    if (i < E)          { s = s0; d = d0; os = o0s; od = o0d; j = i; }
    else if (i < 2 * E) { s = s1; d = d1; os = o1s; od = o1d; j = i - E; }
    else if (i < 3 * E) { s = s2; d = d2; os = o2s; od = o2d; j = i - 2 * E; }
    else if (i < 4 * E) { s = s3; d = d3; os = o3s; od = o3d; j = i - 3 * E; }
    else return;
    atomicAdd(&g_deg[os + __ldg(s + j)], 1);
    atomicAdd(&g_deg[od + __ldg(d + j)], 1);
}

// ---------------- scan phase 1 (+ fused norm over ALL segments) ----------------
#define SCAN_BLK 1024
__global__ void scan1_norm(int total, int nTot, int nDrug, int nGene,
                           int o_dd_d, int o_gd_d, int o_dg_d, int o_gg_d) {
    __shared__ int sh[256];
    const int tid = threadIdx.x;
    const int base = blockIdx.x * SCAN_BLK + tid * 4;
    const int c1 = nDrug, c2 = 2 * nDrug, c3 = 2 * nDrug + nGene;
    int v[4], ssum = 0;
    #pragma unroll
    for (int q = 0; q < 4; q++) {
        int i = base + q, d = 0;
        if (i < total) {
            int idx;
            if (i < c1)      idx = o_dd_d + i;
            else if (i < c2) idx = o_gd_d + i - c1;
            else if (i < c3) idx = o_dg_d + i - c2;
            else             idx = o_gg_d + i - c3;
            d = g_deg[idx];
        }
        v[q] = d; ssum += d;
    }
    sh[tid] = ssum; __syncthreads();
    for (int off = 1; off < 256; off <<= 1) {
        int t = (tid >= off) ? sh[tid - off] : 0;
        __syncthreads();
        sh[tid] += t;
        __syncthreads();
    }
    int run = sh[tid] - ssum;
    if (tid == 255) g_bsum[blockIdx.x] = sh[255];
    #pragma unroll
    for (int q = 0; q < 4; q++) {
        int i = base + q;
        if (i < total) g_base[i] = run;
        run += v[q];
    }
    // fused norm over the full 600k range (each block covers a 2048 slice)
    const int nb = blockIdx.x * 2048;
    #pragma unroll
    for (int q = 0; q < 8; q++) {
        int i = nb + q * 256 + tid;
        if (i < nTot) g_norm[i] = rsqrtf(fmaxf((float)g_deg[i], 1.0f));
    }
}

// ---------------- scan phase 2+3: add block-sum prefix, init cursor ----------------
__global__ void scan23(int total, int nBlk) {
    __shared__ int ssum[256];
    const int tid = threadIdx.x;
    const int sb = blockIdx.x >> 2;   // which SCAN_BLK block this 256-slice belongs to
    int v = 0;
    for (int t = tid; t < sb; t += 256) v += g_bsum[t];
    ssum[tid] = v; __syncthreads();
    for (int off = 128; off > 0; off >>= 1) {
        if (tid < off) ssum[tid] += ssum[tid + off];
        __syncthreads();
    }
    const int add = ssum[0];
    const int idx = blockIdx.x * 256 + tid;
    if (idx < total) {
        int val = g_base[idx] + add;
        g_base[idx] = val;
        g_cursor[idx] = val;
    }
}

// ---------------- binning: ebuf[pos] = src (CSR by dst); segment order dd, gd, dg, gg ----------------
__global__ void bin_all(const int* __restrict__ s0, const int* __restrict__ d0,
                        const int* __restrict__ s1, const int* __restrict__ d1,
                        const int* __restrict__ s2, const int* __restrict__ d2,
                        const int* __restrict__ s3, const int* __restrict__ d3,
                        int E, int nDrug, int nGene) {
    int i = blockIdx.x * blockDim.x + threadIdx.x;
    const int *s, *d; int off, j;
    if (i < E)          { s = s0; d = d0; off = 0;                 j = i; }
    else if (i < 2 * E) { s = s1; d = d1; off = nDrug;             j = i - E; }
    else if (i < 3 * E) { s = s2; d = d2; off = 2 * nDrug;         j = i - 2 * E; }
    else if (i < 4 * E) { s = s3; d = d3; off = 2 * nDrug + nGene; j = i - 3 * E; }
    else return;
    int dd = __ldg(d + j);
    int pos = atomicAdd(&g_cursor[off + dd], 1);
    g_ebuf[pos] = __ldg(s + j);
}

// ---------------- projection GEMM (fp16 m16n16k16), both node types in one launch ----------------
#define HPAD 144
#define CPAD 136
#define GEMMH_SMEM (2 * 128 * HPAD * 2)     // 73728 B

__global__ void __launch_bounds__(256, 2)
gemm_all(const float* __restrict__ xD, const float* __restrict__ xG,
         const float* __restrict__ nsDD, const float* __restrict__ nsDG,
         const float* __restrict__ nsGD, const float* __restrict__ nsGG,
         const float* __restrict__ W_dd, const float* __restrict__ W_dg,
         const float* __restrict__ W_gd, const float* __restrict__ W_gg,
         __half* __restrict__ hD, __half* __restrict__ hG,
         int nDrug, int nGene, int nBlkD) {
    extern __shared__ char smraw[];
    __half* Bs = (__half*)smraw;                  // [128][HPAD]
    __half* As = (__half*)smraw + 128 * HPAD;     // [128][HPAD]
    float*  Cf = (float*)smraw;                   // [128][CPAD] (overlay after MMA)
    const int tid = threadIdx.x, wid = tid >> 5;
    const bool isD = blockIdx.x < nBlkD;
    const int bx = isD ? blockIdx.x : blockIdx.x - nBlkD;
    const int yh = blockIdx.y;
    const float* x  = isD ? xD : xG;
    const int    M  = isD ? nDrug : nGene;
    const float* W  = isD ? (yh ? W_dg : W_dd) : (yh ? W_gg : W_gd);
    const float* ns = isD ? (yh ? nsDG : nsDD) : (yh ? nsGG : nsGD);
    __half* h = isD ? hD : hG;

    for (int i = tid; i < 128 * 32; i += 256) {
        int k = i >> 5, nq = i & 31;
        float4 v = __ldg((const float4*)(W + k * 128) + nq);
        __half2* p = (__half2*)&Bs[k * HPAD + nq * 4];
        p[0] = __floats2half2_rn(v.x, v.y);
        p[1] = __floats2half2_rn(v.z, v.w);
    }

    const int rowBase = bx * 128;
    for (int i = tid; i < 4096; i += 256) {
        int m = i >> 5, kq = i & 31;
        int gr = rowBase + m;
        float4 v = make_float4(0.f, 0.f, 0.f, 0.f);
        if (gr < M) {
            v = __ldg((const float4*)(x + (size_t)gr * DIM) + kq);
            float s = __ldg(ns + gr);
            v.x *= s; v.y *= s; v.z *= s; v.w *= s;
        }
        __half2* p = (__half2*)&As[m * HPAD + kq * 4];
        p[0] = __floats2half2_rn(v.x, v.y);
        p[1] = __floats2half2_rn(v.z, v.w);
    }
    __syncthreads();

    const int wrow = wid * 16;
    wmma::fragment<wmma::accumulator, 16, 16, 16, float> c[8];
    #pragma unroll
    for (int t = 0; t < 8; t++) wmma::fill_fragment(c[t], 0.0f);

    #pragma unroll
    for (int ks = 0; ks < 8; ks++) {
        wmma::fragment<wmma::matrix_a, 16, 16, 16, __half, wmma::row_major> a;
        wmma::load_matrix_sync(a, &As[wrow * HPAD + ks * 16], HPAD);
        #pragma unroll
        for (int t = 0; t < 8; t++) {
            wmma::fragment<wmma::matrix_b, 16, 16, 16, __half, wmma::row_major> b;
            wmma::load_matrix_sync(b, &Bs[(ks * 16) * HPAD + t * 16], HPAD);
            wmma::mma_sync(c[t], a, b, c[t]);
        }
    }
    __syncthreads();

    float* Cw = Cf + wrow * CPAD;
    #pragma unroll
    for (int t = 0; t < 8; t++)
        wmma::store_matrix_sync(&Cw[t * 16], c[t], CPAD, wmma::mem_row_major);
    __syncthreads();

    for (int i = tid; i < 128 * 64; i += 256) {
        int m = i >> 6, c2 = i & 63;
        int gr = rowBase + m;
        if (gr < M) {
            const float* p = &Cf[m * CPAD + c2 * 2];
            __half2* hp = (__half2*)(h + (size_t)gr * 256 + yh * 128);
            hp[c2] = __floats2half2_rn(p[0], p[1]);
        }
    }
}

// ---------------- final gather: 2 warps/node, uint4 loads (2 edges per instr) ----------------
__global__ void __launch_bounds__(256)
gather_out(const float* __restrict__ bias, float* __restrict__ out,
           int nDrug, int nGene,
           int o_dd_d, int o_gd_d, int o_dg_d, int o_gg_d,
           int o_dd_s, int o_dg_s, int o_gd_s, int o_gg_s) {
    __shared__ float red[8][128];
    const int tid  = threadIdx.x;
    const int wid  = tid >> 5, lane = tid & 31;
    const int hl   = lane >> 4, li = lane & 15;
    const int node = blockIdx.x * 4 + (wid >> 1);
    const int list = wid & 1;
    const int nNodes = nDrug + nGene;

    float acc[8];
    #pragma unroll
    for (int k = 0; k < 8; k++) acc[k] = 0.f;
    float nn = 0.f;

    if (node < nNodes) {
        const __half* h; int colOff, b, dg, dentry;
        if (node < nDrug) {
            int r = node; colOff = 0;
            if (list == 0) { h = g_hD; b = __ldg(g_base + r);         dentry = o_dd_d + r; }
            else           { h = g_hG; b = __ldg(g_base + nDrug + r); dentry = o_gd_d + r; }
        } else {
            int r = node - nDrug; colOff = 128;
            if (list == 0) { h = g_hD; b = __ldg(g_base + 2 * nDrug + r);         dentry = o_dg_d + r; }
            else           { h = g_hG; b = __ldg(g_base + 2 * nDrug + nGene + r); dentry = o_gg_d + r; }
        }
        dg = __ldg(g_deg + dentry);
        nn = __ldg(g_norm + dentry);
        if (lane == 0) g_deg[dentry] = 0;   // self-restore (single reader per entry)

        const uint4* hp = (const uint4*)(h + colOff);   // row s: 32 uint4; window = 16
        int j = b; const int e = b + dg;
        for (; j + 8 <= e; j += 8) {        // 4 pairs = 8 edges, all valid
            int s0 = __ldg(g_ebuf + j + 0 + hl);
            int s1 = __ldg(g_ebuf + j + 2 + hl);
            int s2 = __ldg(g_ebuf + j + 4 + hl);
            int s3 = __ldg(g_ebuf + j + 6 + hl);
            uint4 u0 = __ldg(hp + (size_t)s0 * 32 + li);
            uint4 u1 = __ldg(hp + (size_t)s1 * 32 + li);
            uint4 u2 = __ldg(hp + (size_t)s2 * 32 + li);
            uint4 u3 = __ldg(hp + (size_t)s3 * 32 + li);
            #pragma unroll
            for (int q = 0; q < 4; q++) {
                uint4 u = (q == 0) ? u0 : (q == 1) ? u1 : (q == 2) ? u2 : u3;
                const __half2* ph = (const __half2*)&u;
                #pragma unroll
                for (int p2 = 0; p2 < 4; p2++) {
                    float2 f = __half22float2(ph[p2]);
                    acc[p2 * 2] += f.x; acc[p2 * 2 + 1] += f.y;
                }
            }
        }
        for (; j < e; j += 2) {             // tail pairs (predicated)
            int idx = j + hl;
            bool valid = idx < e;
            int s = valid ? __ldg(g_ebuf + idx) : 0;
            uint4 u = __ldg(hp + (size_t)s * 32 + li);
            if (valid) {
                const __half2* ph = (const __half2*)&u;
                #pragma unroll
                for (int p2 = 0; p2 < 4; p2++) {
                    float2 f = __half22float2(ph[p2]);
                    acc[p2 * 2] += f.x; acc[p2 * 2 + 1] += f.y;
                }
            }
        }
    }
    // combine the two half-warps (edge parity), scale by dst norm
    #pragma unroll
    for (int k = 0; k < 8; k++) {
        acc[k] += __shfl_down_sync(0xffffffffu, acc[k], 16);
        acc[k] *= nn;
    }
    if (hl == 0) {
        #pragma unroll
        for (int k = 0; k < 8; k++) red[wid][li * 8 + k] = acc[k];
    }
    __syncthreads();

    if (list == 0 && hl == 0 && node < nNodes) {
        const float* other = &red[wid + 1][li * 8];
        float4 bb0 = __ldg((const float4*)bias + li * 2);
        float4 bb1 = __ldg((const float4*)bias + li * 2 + 1);
        float bbv[8] = {bb0.x, bb0.y, bb0.z, bb0.w, bb1.x, bb1.y, bb1.z, bb1.w};
        float v[8], ss = 0.f;
        #pragma unroll
        for (int k = 0; k < 8; k++) {
            v[k] = fmaxf(acc[k] + other[k] + bbv[k], 0.f);
            ss += v[k] * v[k];
        }
        #pragma unroll
        for (int off = 8; off > 0; off >>= 1)
            ss += __shfl_xor_sync(0x0000ffffu, ss, off);
        float inv = 1.0f / fmaxf(sqrtf(ss), 1e-12f);
        float4 o0 = make_float4(v[0]*inv, v[1]*inv, v[2]*inv, v[3]*inv);
        float4 o1 = make_float4(v[4]*inv, v[5]*inv, v[6]*inv, v[7]*inv);
        float4* op = (float4*)(out + (size_t)node * DIM) + li * 2;
        op[0] = o0; op[1] = o1;
    }

    // self-restore: zero the 4 src-degree segments (unread by this kernel)
    const int gi = blockIdx.x * 256 + tid;
    const int nSrc = 2 * nDrug + 2 * nGene;
    if (gi < nSrc) {
        int idx;
        if (gi < nDrug)              idx = o_dd_s + gi;
        else if (gi < 2 * nDrug)     idx = o_dg_s + gi - nDrug;
        else if (gi < 2*nDrug+nGene) idx = o_gd_s + gi - 2 * nDrug;
        else                         idx = o_gg_s + gi - 2 * nDrug - nGene;
        g_deg[idx] = 0;
    }
}

// ---------------- launch ----------------
extern "C" void kernel_launch(void* const* d_in, const int* in_sizes, int n_in,
                              void* d_out, int out_size) {
    const float* x_drug = (const float*)d_in[0];
    const float* x_gene = (const float*)d_in[1];
    const float* W_dd   = (const float*)d_in[2];
    const float* W_dg   = (const float*)d_in[3];
    const float* W_gd   = (const float*)d_in[4];
    const float* W_gg   = (const float*)d_in[5];
    const float* h_bias = (const float*)d_in[6];
    const int* src_dd = (const int*)d_in[7];   const int* dst_dd = (const int*)d_in[8];
    const int* src_dg = (const int*)d_in[9];   const int* dst_dg = (const int*)d_in[10];
    const int* src_gd = (const int*)d_in[11];  const int* dst_gd = (const int*)d_in[12];
    const int* src_gg = (const int*)d_in[13];  const int* dst_gg = (const int*)d_in[14];
    float* out = (float*)d_out;

    const int E     = in_sizes[7];
    const int nDrug = in_sizes[0] / DIM;
    const int nGene = in_sizes[1] / DIM;

    const int o_dd_s = 0;
    const int o_dd_d = o_dd_s + nDrug;
    const int o_dg_s = o_dd_d + nDrug;
    const int o_dg_d = o_dg_s + nDrug;
    const int o_gd_s = o_dg_d + nGene;
    const int o_gd_d = o_gd_s + nGene;
    const int o_gg_s = o_gd_d + nDrug;
    const int o_gg_d = o_gg_s + nGene;
    const int nTot   = o_gg_d + nGene;          // 600000
    const int nScan  = 2 * nDrug + 2 * nGene;   // 300000

    float* normP;
    __half *hD, *hG;
    cudaGetSymbolAddress((void**)&normP, g_norm);
    cudaGetSymbolAddress((void**)&hD, g_hD);
    cudaGetSymbolAddress((void**)&hG, g_hG);

    // 0: degrees (g_deg zeroed: load-time init on first run, gather_out thereafter)
    const long long totDeg = 4LL * E;
    deg_all<<<(int)((totDeg + 255) / 256), 256>>>(
        src_dd, dst_dd, o_dd_s, o_dd_d,
        src_dg, dst_dg, o_dg_s, o_dg_d,
        src_gd, dst_gd, o_gd_s, o_gd_d,
        src_gg, dst_gg, o_gg_s, o_gg_d, E);

    // 1: dst-degree scan phase1 + all norms
    const int nScanBlk = (nScan + SCAN_BLK - 1) / SCAN_BLK;
    scan1_norm<<<nScanBlk, 256>>>(nScan, nTot, nDrug, nGene,
                                  o_dd_d, o_gd_d, o_dg_d, o_gg_d);

    // 2: scan phases 2+3 fused
    scan23<<<(nScan + 255) / 256, 256>>>(nScan, nScanBlk);

    // 3 (profiled): both projection GEMMs in one launch
    cudaFuncSetAttribute(gemm_all, cudaFuncAttributeMaxDynamicSharedMemorySize, GEMMH_SMEM);
    const int nBlkD = (nDrug + 127) / 128;
    const int nBlkG = (nGene + 127) / 128;
    dim3 gAll(nBlkD + nBlkG, 2);
    gemm_all<<<gAll, 256, GEMMH_SMEM>>>(
        x_drug, x_gene,
        normP + o_dd_s, normP + o_dg_s, normP + o_gd_s, normP + o_gg_s,
        W_dd, W_dg, W_gd, W_gg, hD, hG, nDrug, nGene, nBlkD);

    // 4: binning
    bin_all<<<(int)((totDeg + 255) / 256), 256>>>(
        src_dd, dst_dd,
        src_gd, dst_gd,
        src_dg, dst_dg,
        src_gg, dst_gg, E, nDrug, nGene);

    // 5: gather + epilogue (+ state restore)
    gather_out<<<(nDrug + nGene + 3) / 4, 256>>>(
        h_bias, out, nDrug, nGene,
        o_dd_d, o_gd_d, o_dg_d, o_gg_d,
        o_dd_s, o_dg_s, o_gd_s, o_gg_s);
}

// round 10
// speedup vs baseline: 1.6541x; 1.6541x over previous
#include <cuda_runtime.h>
#include <cuda_fp16.h>
#include <cstdint>
#include <math.h>
#include <mma.h>

using namespace nvcuda;

#define DIM 128

// ---------------- scratch (device globals; no allocation allowed) ----------------
__device__ int    g_deg [600000];
__device__ float  g_norm[600000];
__device__ int    g_base  [300000];   // CSR row starts: [dd | gd | dg | gg] (by dst)
__device__ int    g_cursor[300000];
__device__ int    g_bsum  [512];
__device__ int    g_ebuf  [2400000];  // binned src indices
__device__ __half g_hD[100000ull * 256];  // drug proj: cols 0-127 = x@W_dd, 128-255 = x@W_dg
__device__ __half g_hG[ 50000ull * 256];  // gene proj: cols 0-127 = x@W_gd, 128-255 = x@W_gg

// ---------------- zero deg ----------------
__global__ void zero_deg() {
    int i = blockIdx.x * blockDim.x + threadIdx.x;
    if (i < 600000 / 4) ((int4*)g_deg)[i] = make_int4(0, 0, 0, 0);
}

// ---------------- degree counting (all 4 etypes) ----------------
__global__ void deg_all(const int* __restrict__ s0, const int* __restrict__ d0, int o0s, int o0d,
                        const int* __restrict__ s1, const int* __restrict__ d1, int o1s, int o1d,
                        const int* __restrict__ s2, const int* __restrict__ d2, int o2s, int o2d,
                        const int* __restrict__ s3, const int* __restrict__ d3, int o3s, int o3d,
                        int E) {
    int i = blockIdx.x * blockDim.x + threadIdx.x;
    const int *s, *d; int os, od, j;
    if (i < E)          { s = s0; d = d0; os = o0s; od = o0d; j = i; }
    else if (i < 2 * E) { s = s1; d = d1; os = o1s; od = o1d; j = i - E; }
    else if (i < 3 * E) { s = s2; d = d2; os = o2s; od = o2d; j = i - 2 * E; }
    else if (i < 4 * E) { s = s3; d = d3; os = o3s; od = o3d; j = i - 3 * E; }
    else return;
    atomicAdd(&g_deg[os + __ldg(s + j)], 1);
    atomicAdd(&g_deg[od + __ldg(d + j)], 1);
}

__global__ void norm_kernel(int n) {
    int i = blockIdx.x * blockDim.x + threadIdx.x;
    if (i < n) g_norm[i] = rsqrtf(fmaxf((float)g_deg[i], 1.0f));
}

// ---------------- 3-phase exclusive scan over concatenated dst degrees ----------------
#define SCAN_BLK 1024
__global__ void scan1(int total, int nDrug, int nGene,
                      int o_dd_d, int o_gd_d, int o_dg_d, int o_gg_d) {
    __shared__ int sh[256];
    const int tid = threadIdx.x;
    const int base = blockIdx.x * SCAN_BLK + tid * 4;
    const int c1 = nDrug, c2 = 2 * nDrug, c3 = 2 * nDrug + nGene;
    int v[4], ssum = 0;
    #pragma unroll
    for (int q = 0; q < 4; q++) {
        int i = base + q, d = 0;
        if (i < total) {
            int idx;
            if (i < c1)      idx = o_dd_d + i;
            else if (i < c2) idx = o_gd_d + i - c1;
            else if (i < c3) idx = o_dg_d + i - c2;
            else             idx = o_gg_d + i - c3;
            d = g_deg[idx];
        }
        v[q] = d; ssum += d;
    }
    sh[tid] = ssum; __syncthreads();
    for (int off = 1; off < 256; off <<= 1) {
        int t = (tid >= off) ? sh[tid - off] : 0;
        __syncthreads();
        sh[tid] += t;
        __syncthreads();
    }
    int run = sh[tid] - ssum;
    if (tid == 255) g_bsum[blockIdx.x] = sh[255];
    #pragma unroll
    for (int q = 0; q < 4; q++) {
        int i = base + q;
        if (i < total) g_base[i] = run;
        run += v[q];
    }
}

__global__ void scan2(int n) {
    __shared__ int sh[512];
    int tid = threadIdx.x;
    int v = (tid < n) ? g_bsum[tid] : 0;
    sh[tid] = v; __syncthreads();
    for (int off = 1; off < 512; off <<= 1) {
        int t = (tid >= off) ? sh[tid - off] : 0;
        __syncthreads();
        sh[tid] += t;
        __syncthreads();
    }
    if (tid < n) g_bsum[tid] = sh[tid] - v;
}

__global__ void scan3(int total) {
    int i = blockIdx.x * blockDim.x + threadIdx.x;
    if (i < total) {
        int v = g_base[i] + g_bsum[i / SCAN_BLK];
        g_base[i] = v;
        g_cursor[i] = v;
    }
}

// ---------------- binning: ebuf[pos] = src (CSR by dst); segment order dd, gd, dg, gg ----------------
__global__ void bin_all(const int* __restrict__ s0, const int* __restrict__ d0,
                        const int* __restrict__ s1, const int* __restrict__ d1,
                        const int* __restrict__ s2, const int* __restrict__ d2,
                        const int* __restrict__ s3, const int* __restrict__ d3,
                        int E, int nDrug, int nGene) {
    int i = blockIdx.x * blockDim.x + threadIdx.x;
    const int *s, *d; int off, j;
    if (i < E)          { s = s0; d = d0; off = 0;                 j = i; }
    else if (i < 2 * E) { s = s1; d = d1; off = nDrug;             j = i - E; }
    else if (i < 3 * E) { s = s2; d = d2; off = 2 * nDrug;         j = i - 2 * E; }
    else if (i < 4 * E) { s = s3; d = d3; off = 2 * nDrug + nGene; j = i - 3 * E; }
    else return;
    int dd = __ldg(d + j);
    int pos = atomicAdd(&g_cursor[off + dd], 1);
    g_ebuf[pos] = __ldg(s + j);
}

// ---------------- projection GEMM (fp16 m16n16k16): h[:, yh*128:+128] = x @ W_yh ----------------
// A (unscaled x) staged ONCE, reused for both yh. C dumped via 64-row buffer in 2 phases.
// smem: As half[128][144] | Bs half[128][144] | Cf float[64][136]
#define HPAD 144
#define CPAD 136
#define GEMMH_SMEM (2 * 128 * HPAD * 2 + 64 * CPAD * 4)   // 73728 + 34816 = 108544 B

__global__ void __launch_bounds__(256, 2)
gemm_h(const float* __restrict__ x,
       const float* __restrict__ W0, const float* __restrict__ W1,
       __half* __restrict__ h, int M) {
    extern __shared__ char smraw[];
    __half* As = (__half*)smraw;                       // [128][HPAD]
    __half* Bs = (__half*)smraw + 128 * HPAD;          // [128][HPAD]
    float*  Cf = (float*)(smraw + 2 * 128 * HPAD * 2); // [64][CPAD]
    const int tid = threadIdx.x, wid = tid >> 5;
    const int rowBase = blockIdx.x * 128;

    // Stage A = x rows (unscaled) -> half.
    for (int i = tid; i < 4096; i += 256) {
        int m = i >> 5, kq = i & 31;
        int gr = rowBase + m;
        float4 v = make_float4(0.f, 0.f, 0.f, 0.f);
        if (gr < M) v = __ldg((const float4*)(x + (size_t)gr * DIM) + kq);
        __half2* p = (__half2*)&As[m * HPAD + kq * 4];
        p[0] = __floats2half2_rn(v.x, v.y);
        p[1] = __floats2half2_rn(v.z, v.w);
    }

    const int wrow = wid * 16;
    #pragma unroll
    for (int yh = 0; yh < 2; yh++) {
        const float* W = yh ? W1 : W0;
        // Stage B(yh). (Bs not read by anyone at this point: yh=0 -> nothing yet;
        // yh=1 -> previous MMA completed before the epilogue syncs below.)
        for (int i = tid; i < 128 * 32; i += 256) {
            int k = i >> 5, nq = i & 31;
            float4 v = __ldg((const float4*)(W + k * 128) + nq);
            __half2* p = (__half2*)&Bs[k * HPAD + nq * 4];
            p[0] = __floats2half2_rn(v.x, v.y);
            p[1] = __floats2half2_rn(v.z, v.w);
        }
        __syncthreads();   // A (first iter) + B staged

        wmma::fragment<wmma::accumulator, 16, 16, 16, float> c[8];
        #pragma unroll
        for (int t = 0; t < 8; t++) wmma::fill_fragment(c[t], 0.0f);
        #pragma unroll
        for (int ks = 0; ks < 8; ks++) {
            wmma::fragment<wmma::matrix_a, 16, 16, 16, __half, wmma::row_major> a;
            wmma::load_matrix_sync(a, &As[wrow * HPAD + ks * 16], HPAD);
            #pragma unroll
            for (int t = 0; t < 8; t++) {
                wmma::fragment<wmma::matrix_b, 16, 16, 16, __half, wmma::row_major> b;
                wmma::load_matrix_sync(b, &Bs[(ks * 16) * HPAD + t * 16], HPAD);
                wmma::mma_sync(c[t], a, b, c[t]);
            }
        }

        // Epilogue: two phases of 64 rows through Cf.
        #pragma unroll
        for (int phase = 0; phase < 2; phase++) {
            __syncthreads();   // Cf free (and, phase 0: all MMAs done -> Bs restage-safe later)
            if ((wid >> 2) == phase) {
                float* Cw = Cf + (wid & 3) * 16 * CPAD;
                #pragma unroll
                for (int t = 0; t < 8; t++)
                    wmma::store_matrix_sync(&Cw[t * 16], c[t], CPAD, wmma::mem_row_major);
            }
            __syncthreads();
            for (int i = tid; i < 64 * 64; i += 256) {
                int m = i >> 6, c2 = i & 63;
                int gr = rowBase + phase * 64 + m;
                if (gr < M) {
                    const float* p = &Cf[m * CPAD + c2 * 2];
                    __half2* hp = (__half2*)(h + (size_t)gr * 256 + yh * 128);
                    hp[c2] = __floats2half2_rn(p[0], p[1]);
                }
            }
        }
        __syncthreads();   // h-writes of this yh done before Cf/Bs reuse
    }
}

// ---------------- final gather: TWO warps per dst node; per-edge src-norm scaling ----------------
// out[r] = l2norm(relu( nd0 * Σ ns0[s]*h0[s] + nd1 * Σ ns1[s]*h1[s] + bias ))
__global__ void __launch_bounds__(256)
gather_out(const float* __restrict__ bias, float* __restrict__ out,
           int nDrug, int nGene,
           int o_dd_d, int o_gd_d, int o_dg_d, int o_gg_d,
           int o_dd_s, int o_gd_s, int o_dg_s, int o_gg_s) {
    __shared__ float4 red[8][32];
    const int tid  = threadIdx.x;
    const int wid  = tid >> 5, lane = tid & 31;
    const int node = blockIdx.x * 4 + (wid >> 1);
    const int list = wid & 1;
    const int nNodes = nDrug + nGene;

    float4 acc = make_float4(0.f, 0.f, 0.f, 0.f);
    float nn = 0.f;

    if (node < nNodes) {
        const __half* h; const float* ns; int colOff, b, dg, odst;
        if (node < nDrug) {
            int r = node; colOff = 0;
            if (list == 0) { h = g_hD; ns = g_norm + o_dd_s; b = __ldg(g_base + r);         odst = o_dd_d; }
            else           { h = g_hG; ns = g_norm + o_gd_s; b = __ldg(g_base + nDrug + r); odst = o_gd_d; }
            dg = __ldg(g_deg + odst + r); nn = __ldg(g_norm + odst + r);
        } else {
            int r = node - nDrug; colOff = 128;
            if (list == 0) { h = g_hD; ns = g_norm + o_dg_s; b = __ldg(g_base + 2 * nDrug + r);         odst = o_dg_d; }
            else           { h = g_hG; ns = g_norm + o_gg_s; b = __ldg(g_base + 2 * nDrug + nGene + r); odst = o_gg_d; }
            dg = __ldg(g_deg + odst + r); nn = __ldg(g_norm + odst + r);
        }

        const uint2* hp = (const uint2*)(h + colOff);   // row s at hp + s*64 + lane
        int j = b; const int e = b + dg;
        for (; j + 8 <= e; j += 8) {
            int s[8];
            #pragma unroll
            for (int q = 0; q < 8; q++) s[q] = __ldg(g_ebuf + j + q);
            float w[8];
            #pragma unroll
            for (int q = 0; q < 8; q++) w[q] = __ldg(ns + s[q]);
            uint2 u[8];
            #pragma unroll
            for (int q = 0; q < 8; q++) u[q] = __ldg(hp + (size_t)s[q] * 64 + lane);
            #pragma unroll
            for (int q = 0; q < 8; q++) {
                float2 a = __half22float2(*(const __half2*)&u[q].x);
                float2 c = __half22float2(*(const __half2*)&u[q].y);
                acc.x = fmaf(w[q], a.x, acc.x);
                acc.y = fmaf(w[q], a.y, acc.y);
                acc.z = fmaf(w[q], c.x, acc.z);
                acc.w = fmaf(w[q], c.y, acc.w);
            }
        }
        for (; j < e; j++) {
            int s = __ldg(g_ebuf + j);
            float w = __ldg(ns + s);
            uint2 u = __ldg(hp + (size_t)s * 64 + lane);
            float2 a = __half22float2(*(const __half2*)&u.x);
            float2 c = __half22float2(*(const __half2*)&u.y);
            acc.x = fmaf(w, a.x, acc.x);
            acc.y = fmaf(w, a.y, acc.y);
            acc.z = fmaf(w, c.x, acc.z);
            acc.w = fmaf(w, c.y, acc.w);
        }
    }
    acc.x *= nn; acc.y *= nn; acc.z *= nn; acc.w *= nn;
    red[wid][lane] = acc;
    __syncthreads();

    if (list == 0 && node < nNodes) {
        float4 o = red[wid + 1][lane];
        float4 bb = __ldg((const float4*)bias + lane);
        float4 v;
        v.x = fmaxf(acc.x + o.x + bb.x, 0.f);
        v.y = fmaxf(acc.y + o.y + bb.y, 0.f);
        v.z = fmaxf(acc.z + o.z + bb.z, 0.f);
        v.w = fmaxf(acc.w + o.w + bb.w, 0.f);

        float ss = v.x * v.x + v.y * v.y + v.z * v.z + v.w * v.w;
        #pragma unroll
        for (int off = 16; off > 0; off >>= 1)
            ss += __shfl_xor_sync(0xffffffffu, ss, off);
        float inv = 1.0f / fmaxf(sqrtf(ss), 1e-12f);
        v.x *= inv; v.y *= inv; v.z *= inv; v.w *= inv;

        *((float4*)(out + (size_t)node * DIM) + lane) = v;
    }
}

// ---------------- launch ----------------
extern "C" void kernel_launch(void* const* d_in, const int* in_sizes, int n_in,
                              void* d_out, int out_size) {
    const float* x_drug = (const float*)d_in[0];
    const float* x_gene = (const float*)d_in[1];
    const float* W_dd   = (const float*)d_in[2];
    const float* W_dg   = (const float*)d_in[3];
    const float* W_gd   = (const float*)d_in[4];
    const float* W_gg   = (const float*)d_in[5];
    const float* h_bias = (const float*)d_in[6];
    const int* src_dd = (const int*)d_in[7];   const int* dst_dd = (const int*)d_in[8];
    const int* src_dg = (const int*)d_in[9];   const int* dst_dg = (const int*)d_in[10];
    const int* src_gd = (const int*)d_in[11];  const int* dst_gd = (const int*)d_in[12];
    const int* src_gg = (const int*)d_in[13];  const int* dst_gg = (const int*)d_in[14];
    float* out = (float*)d_out;

    const int E     = in_sizes[7];
    const int nDrug = in_sizes[0] / DIM;
    const int nGene = in_sizes[1] / DIM;

    const int o_dd_s = 0;
    const int o_dd_d = o_dd_s + nDrug;
    const int o_dg_s = o_dd_d + nDrug;
    const int o_dg_d = o_dg_s + nDrug;
    const int o_gd_s = o_dg_d + nGene;
    const int o_gd_d = o_gd_s + nGene;
    const int o_gg_s = o_gd_d + nDrug;
    const int o_gg_d = o_gg_s + nGene;
    const int nTot   = o_gg_d + nGene;          // 600000
    const int nScan  = 2 * nDrug + 2 * nGene;   // 300000

    __half *hD, *hG;
    cudaGetSymbolAddress((void**)&hD, g_hD);
    cudaGetSymbolAddress((void**)&hG, g_hG);

    zero_deg<<<(600000 / 4 + 255) / 256, 256>>>();

    const long long totDeg = 4LL * E;
    deg_all<<<(int)((totDeg + 255) / 256), 256>>>(
        src_dd, dst_dd, o_dd_s, o_dd_d,
        src_dg, dst_dg, o_dg_s, o_dg_d,
        src_gd, dst_gd, o_gd_s, o_gd_d,
        src_gg, dst_gg, o_gg_s, o_gg_d, E);

    norm_kernel<<<(nTot + 255) / 256, 256>>>(nTot);

    const int nScanBlk = (nScan + SCAN_BLK - 1) / SCAN_BLK;
    scan1<<<nScanBlk, 256>>>(nScan, nDrug, nGene, o_dd_d, o_gd_d, o_dg_d, o_gg_d);
    scan2<<<1, 512>>>(nScanBlk);
    scan3<<<(nScan + 255) / 256, 256>>>(nScan);

    bin_all<<<(int)((totDeg + 255) / 256), 256>>>(
        src_dd, dst_dd,
        src_gd, dst_gd,
        src_dg, dst_dg,
        src_gg, dst_gg, E, nDrug, nGene);

    // projection GEMMs: h = x @ W (unscaled A shared across both etype halves)
    cudaFuncSetAttribute(gemm_h, cudaFuncAttributeMaxDynamicSharedMemorySize, GEMMH_SMEM);
    gemm_h<<<(nDrug + 127) / 128, 256, GEMMH_SMEM>>>(x_drug, W_dd, W_dg, hD, nDrug);
    gemm_h<<<(nGene + 127) / 128, 256, GEMMH_SMEM>>>(x_gene, W_gd, W_gg, hG, nGene);

    // final gather + epilogue: two warps per dst node, 4 nodes per block
    gather_out<<<(nDrug + nGene + 3) / 4, 256>>>(
        h_bias, out, nDrug, nGene,
        o_dd_d, o_gd_d, o_dg_d, o_gg_d,
        o_dd_s, o_gd_s, o_dg_s, o_gg_s);
}

// round 11
// speedup vs baseline: 2.5320x; 1.5308x over previous
#include <cuda_runtime.h>
#include <cuda_fp16.h>
#include <cstdint>
#include <math.h>
#include <mma.h>

using namespace nvcuda;

#define DIM 128

// ---------------- scratch (device globals; no allocation allowed) ----------------
__device__ int    g_deg [600000];
__device__ float  g_norm[600000];
__device__ int    g_base  [300000];   // CSR row starts: [dd | gd | dg | gg] (by dst)
__device__ int    g_cursor[300000];
__device__ int    g_bsum  [512];
__device__ int    g_ebuf  [2400000];  // binned src indices
__device__ __half g_hD[100000ull * 256];  // drug proj: cols 0-127 = dd, 128-255 = dg
__device__ __half g_hG[ 50000ull * 256];  // gene proj: cols 0-127 = gd, 128-255 = gg

// ---------------- zero deg ----------------
__global__ void zero_deg() {
    int i = blockIdx.x * blockDim.x + threadIdx.x;
    if (i < 600000 / 4) ((int4*)g_deg)[i] = make_int4(0, 0, 0, 0);
}

// ---------------- degree counting (all 4 etypes) ----------------
__global__ void deg_all(const int* __restrict__ s0, const int* __restrict__ d0, int o0s, int o0d,
                        const int* __restrict__ s1, const int* __restrict__ d1, int o1s, int o1d,
                        const int* __restrict__ s2, const int* __restrict__ d2, int o2s, int o2d,
                        const int* __restrict__ s3, const int* __restrict__ d3, int o3s, int o3d,
                        int E) {
    int i = blockIdx.x * blockDim.x + threadIdx.x;
    const int *s, *d; int os, od, j;
    if (i < E)          { s = s0; d = d0; os = o0s; od = o0d; j = i; }
    else if (i < 2 * E) { s = s1; d = d1; os = o1s; od = o1d; j = i - E; }
    else if (i < 3 * E) { s = s2; d = d2; os = o2s; od = o2d; j = i - 2 * E; }
    else if (i < 4 * E) { s = s3; d = d3; os = o3s; od = o3d; j = i - 3 * E; }
    else return;
    atomicAdd(&g_deg[os + __ldg(s + j)], 1);
    atomicAdd(&g_deg[od + __ldg(d + j)], 1);
}

__global__ void norm_kernel(int n) {
    int i = blockIdx.x * blockDim.x + threadIdx.x;
    if (i < n) g_norm[i] = rsqrtf(fmaxf((float)g_deg[i], 1.0f));
}

// ---------------- 3-phase exclusive scan over concatenated dst degrees ----------------
#define SCAN_BLK 1024
__global__ void scan1(int total, int nDrug, int nGene,
                      int o_dd_d, int o_gd_d, int o_dg_d, int o_gg_d) {
    __shared__ int sh[256];
    const int tid = threadIdx.x;
    const int base = blockIdx.x * SCAN_BLK + tid * 4;
    const int c1 = nDrug, c2 = 2 * nDrug, c3 = 2 * nDrug + nGene;
    int v[4], ssum = 0;
    #pragma unroll
    for (int q = 0; q < 4; q++) {
        int i = base + q, d = 0;
        if (i < total) {
            int idx;
            if (i < c1)      idx = o_dd_d + i;
            else if (i < c2) idx = o_gd_d + i - c1;
            else if (i < c3) idx = o_dg_d + i - c2;
            else             idx = o_gg_d + i - c3;
            d = g_deg[idx];
        }
        v[q] = d; ssum += d;
    }
    sh[tid] = ssum; __syncthreads();
    for (int off = 1; off < 256; off <<= 1) {
        int t = (tid >= off) ? sh[tid - off] : 0;
        __syncthreads();
        sh[tid] += t;
        __syncthreads();
    }
    int run = sh[tid] - ssum;
    if (tid == 255) g_bsum[blockIdx.x] = sh[255];
    #pragma unroll
    for (int q = 0; q < 4; q++) {
        int i = base + q;
        if (i < total) g_base[i] = run;
        run += v[q];
    }
}

__global__ void scan2(int n) {
    __shared__ int sh[512];
    int tid = threadIdx.x;
    int v = (tid < n) ? g_bsum[tid] : 0;
    sh[tid] = v; __syncthreads();
    for (int off = 1; off < 512; off <<= 1) {
        int t = (tid >= off) ? sh[tid - off] : 0;
        __syncthreads();
        sh[tid] += t;
        __syncthreads();
    }
    if (tid < n) g_bsum[tid] = sh[tid] - v;
}

__global__ void scan3(int total) {
    int i = blockIdx.x * blockDim.x + threadIdx.x;
    if (i < total) {
        int v = g_base[i] + g_bsum[i / SCAN_BLK];
        g_base[i] = v;
        g_cursor[i] = v;
    }
}

// ---------------- binning: ebuf[pos] = src (CSR by dst); segment order dd, gd, dg, gg ----------------
__global__ void bin_all(const int* __restrict__ s0, const int* __restrict__ d0,
                        const int* __restrict__ s1, const int* __restrict__ d1,
                        const int* __restrict__ s2, const int* __restrict__ d2,
                        const int* __restrict__ s3, const int* __restrict__ d3,
                        int E, int nDrug, int nGene) {
    int i = blockIdx.x * blockDim.x + threadIdx.x;
    const int *s, *d; int off, j;
    if (i < E)          { s = s0; d = d0; off = 0;                 j = i; }
    else if (i < 2 * E) { s = s1; d = d1; off = nDrug;             j = i - E; }
    else if (i < 3 * E) { s = s2; d = d2; off = 2 * nDrug;         j = i - 2 * E; }
    else if (i < 4 * E) { s = s3; d = d3; off = 2 * nDrug + nGene; j = i - 3 * E; }
    else return;
    int dd = __ldg(d + j);
    int pos = atomicAdd(&g_cursor[off + dd], 1);
    g_ebuf[pos] = __ldg(s + j);
}

// ---------------- projection GEMM (fp16 m16n16k16): h[:, yh*128:+128] = (nsrc ⊙ x) @ W ----------------
// 512 threads / 16 warps: warp -> 16 rows x 64 cols (4 tiles). 32 warps/SM at 2 CTAs.
// smem: Bs half[128][136] | As half[128][136]  overlaid by  Cf float[128][136]
#define HPAD 136
#define CPAD 136
#define GEMMH_SMEM (2 * 128 * HPAD * 2)     // 69632 B  (== 128*CPAD*4 overlay)

__global__ void __launch_bounds__(512, 2)
gemm_h(const float* __restrict__ x,
       const float* __restrict__ ns0, const float* __restrict__ ns1,
       const float* __restrict__ W0, const float* __restrict__ W1,
       __half* __restrict__ h, int M) {
    extern __shared__ char smraw[];
    __half* Bs = (__half*)smraw;                  // [128][HPAD]
    __half* As = (__half*)smraw + 128 * HPAD;     // [128][HPAD]
    float*  Cf = (float*)smraw;                   // [128][CPAD] (overlay after MMA)
    const int tid = threadIdx.x, wid = tid >> 5;
    const int yh = blockIdx.y;
    const float* W  = yh ? W1  : W0;
    const float* ns = yh ? ns1 : ns0;

    // Stage W[k][n] -> half (coalesced over n).
    for (int i = tid; i < 128 * 32; i += 512) {
        int k = i >> 5, nq = i & 31;
        float4 v = __ldg((const float4*)(W + k * 128) + nq);
        __half2* p = (__half2*)&Bs[k * HPAD + nq * 4];
        p[0] = __floats2half2_rn(v.x, v.y);
        p[1] = __floats2half2_rn(v.z, v.w);
    }

    // Stage A = norm_src-scaled x rows -> half.
    const int rowBase = blockIdx.x * 128;
    for (int i = tid; i < 4096; i += 512) {
        int m = i >> 5, kq = i & 31;
        int gr = rowBase + m;
        float4 v = make_float4(0.f, 0.f, 0.f, 0.f);
        if (gr < M) {
            v = __ldg((const float4*)(x + (size_t)gr * DIM) + kq);
            float s = __ldg(ns + gr);
            v.x *= s; v.y *= s; v.z *= s; v.w *= s;
        }
        __half2* p = (__half2*)&As[m * HPAD + kq * 4];
        p[0] = __floats2half2_rn(v.x, v.y);
        p[1] = __floats2half2_rn(v.z, v.w);
    }
    __syncthreads();

    const int wrow = (wid >> 1) * 16;      // 8 row groups
    const int wcol = (wid & 1) * 64;       // 2 col halves
    wmma::fragment<wmma::accumulator, 16, 16, 16, float> c[4];
    #pragma unroll
    for (int t = 0; t < 4; t++) wmma::fill_fragment(c[t], 0.0f);

    #pragma unroll
    for (int ks = 0; ks < 8; ks++) {
        wmma::fragment<wmma::matrix_a, 16, 16, 16, __half, wmma::row_major> a;
        wmma::load_matrix_sync(a, &As[wrow * HPAD + ks * 16], HPAD);
        #pragma unroll
        for (int t = 0; t < 4; t++) {
            wmma::fragment<wmma::matrix_b, 16, 16, 16, __half, wmma::row_major> b;
            wmma::load_matrix_sync(b, &Bs[(ks * 16) * HPAD + wcol + t * 16], HPAD);
            wmma::mma_sync(c[t], a, b, c[t]);
        }
    }
    __syncthreads();   // stage fully consumed -> safe to overlay C

    float* Cw = Cf + wrow * CPAD + wcol;
    #pragma unroll
    for (int t = 0; t < 4; t++)
        wmma::store_matrix_sync(&Cw[t * 16], c[t], CPAD, wmma::mem_row_major);
    __syncthreads();

    // Coalesced fp16 write: consecutive threads -> consecutive half2 columns.
    for (int i = tid; i < 128 * 64; i += 512) {
        int m = i >> 6, c2 = i & 63;
        int gr = rowBase + m;
        if (gr < M) {
            const float* p = &Cf[m * CPAD + c2 * 2];
            __half2* hp = (__half2*)(h + (size_t)gr * 256 + yh * 128);
            hp[c2] = __floats2half2_rn(p[0], p[1]);
        }
    }
}

// ---------------- final gather: TWO warps per dst node (one per etype list) ----------------
__global__ void __launch_bounds__(256)
gather_out(const float* __restrict__ bias, float* __restrict__ out,
           int nDrug, int nGene,
           int o_dd_d, int o_gd_d, int o_dg_d, int o_gg_d) {
    __shared__ float4 red[8][32];
    const int tid  = threadIdx.x;
    const int wid  = tid >> 5, lane = tid & 31;
    const int node = blockIdx.x * 4 + (wid >> 1);
    const int list = wid & 1;
    const int nNodes = nDrug + nGene;

    float4 acc = make_float4(0.f, 0.f, 0.f, 0.f);
    float nn = 0.f;

    if (node < nNodes) {
        const __half* h; int colOff, b, dg, odst;
        if (node < nDrug) {
            int r = node; colOff = 0;
            if (list == 0) { h = g_hD; b = __ldg(g_base + r);         odst = o_dd_d; }
            else           { h = g_hG; b = __ldg(g_base + nDrug + r); odst = o_gd_d; }
            dg = __ldg(g_deg + odst + r); nn = __ldg(g_norm + odst + r);
        } else {
            int r = node - nDrug; colOff = 128;
            if (list == 0) { h = g_hD; b = __ldg(g_base + 2 * nDrug + r);         odst = o_dg_d; }
            else           { h = g_hG; b = __ldg(g_base + 2 * nDrug + nGene + r); odst = o_gg_d; }
            dg = __ldg(g_deg + odst + r); nn = __ldg(g_norm + odst + r);
        }

        const uint2* hp = (const uint2*)(h + colOff);
        int j = b; const int e = b + dg;
        for (; j + 8 <= e; j += 8) {
            int s[8];
            #pragma unroll
            for (int q = 0; q < 8; q++) s[q] = __ldg(g_ebuf + j + q);
            uint2 u[8];
            #pragma unroll
            for (int q = 0; q < 8; q++) u[q] = __ldg(hp + (size_t)s[q] * 64 + lane);
            #pragma unroll
            for (int q = 0; q < 8; q++) {
                float2 a = __half22float2(*(const __half2*)&u[q].x);
                float2 c = __half22float2(*(const __half2*)&u[q].y);
                acc.x += a.x; acc.y += a.y; acc.z += c.x; acc.w += c.y;
            }
        }
        for (; j + 2 <= e; j += 2) {
            int s0 = __ldg(g_ebuf + j), s1 = __ldg(g_ebuf + j + 1);
            uint2 u0 = __ldg(hp + (size_t)s0 * 64 + lane);
            uint2 u1 = __ldg(hp + (size_t)s1 * 64 + lane);
            float2 a0 = __half22float2(*(const __half2*)&u0.x);
            float2 c0 = __half22float2(*(const __half2*)&u0.y);
            float2 a1 = __half22float2(*(const __half2*)&u1.x);
            float2 c1 = __half22float2(*(const __half2*)&u1.y);
            acc.x += a0.x + a1.x; acc.y += a0.y + a1.y;
            acc.z += c0.x + c1.x; acc.w += c0.y + c1.y;
        }
        if (j < e) {
            int s = __ldg(g_ebuf + j);
            uint2 u = __ldg(hp + (size_t)s * 64 + lane);
            float2 a = __half22float2(*(const __half2*)&u.x);
            float2 c = __half22float2(*(const __half2*)&u.y);
            acc.x += a.x; acc.y += a.y; acc.z += c.x; acc.w += c.y;
        }
    }
    acc.x *= nn; acc.y *= nn; acc.z *= nn; acc.w *= nn;
    red[wid][lane] = acc;
    __syncthreads();

    if (list == 0 && node < nNodes) {
        float4 o = red[wid + 1][lane];
        float4 bb = __ldg((const float4*)bias + lane);
        float4 v;
        v.x = fmaxf(acc.x + o.x + bb.x, 0.f);
        v.y = fmaxf(acc.y + o.y + bb.y, 0.f);
        v.z = fmaxf(acc.z + o.z + bb.z, 0.f);
        v.w = fmaxf(acc.w + o.w + bb.w, 0.f);

        float ss = v.x * v.x + v.y * v.y + v.z * v.z + v.w * v.w;
        #pragma unroll
        for (int off = 16; off > 0; off >>= 1)
            ss += __shfl_xor_sync(0xffffffffu, ss, off);
        float inv = 1.0f / fmaxf(sqrtf(ss), 1e-12f);
        v.x *= inv; v.y *= inv; v.z *= inv; v.w *= inv;

        *((float4*)(out + (size_t)node * DIM) + lane) = v;
    }
}

// ---------------- launch ----------------
extern "C" void kernel_launch(void* const* d_in, const int* in_sizes, int n_in,
                              void* d_out, int out_size) {
    const float* x_drug = (const float*)d_in[0];
    const float* x_gene = (const float*)d_in[1];
    const float* W_dd   = (const float*)d_in[2];
    const float* W_dg   = (const float*)d_in[3];
    const float* W_gd   = (const float*)d_in[4];
    const float* W_gg   = (const float*)d_in[5];
    const float* h_bias = (const float*)d_in[6];
    const int* src_dd = (const int*)d_in[7];   const int* dst_dd = (const int*)d_in[8];
    const int* src_dg = (const int*)d_in[9];   const int* dst_dg = (const int*)d_in[10];
    const int* src_gd = (const int*)d_in[11];  const int* dst_gd = (const int*)d_in[12];
    const int* src_gg = (const int*)d_in[13];  const int* dst_gg = (const int*)d_in[14];
    float* out = (float*)d_out;

    const int E     = in_sizes[7];
    const int nDrug = in_sizes[0] / DIM;
    const int nGene = in_sizes[1] / DIM;

    const int o_dd_s = 0;
    const int o_dd_d = o_dd_s + nDrug;
    const int o_dg_s = o_dd_d + nDrug;
    const int o_dg_d = o_dg_s + nDrug;
    const int o_gd_s = o_dg_d + nGene;
    const int o_gd_d = o_gd_s + nGene;
    const int o_gg_s = o_gd_d + nDrug;
    const int o_gg_d = o_gg_s + nGene;
    const int nTot   = o_gg_d + nGene;          // 600000
    const int nScan  = 2 * nDrug + 2 * nGene;   // 300000

    float* normP;
    __half *hD, *hG;
    cudaGetSymbolAddress((void**)&normP, g_norm);
    cudaGetSymbolAddress((void**)&hD, g_hD);
    cudaGetSymbolAddress((void**)&hG, g_hG);

    zero_deg<<<(600000 / 4 + 255) / 256, 256>>>();

    const long long totDeg = 4LL * E;
    deg_all<<<(int)((totDeg + 255) / 256), 256>>>(
        src_dd, dst_dd, o_dd_s, o_dd_d,
        src_dg, dst_dg, o_dg_s, o_dg_d,
        src_gd, dst_gd, o_gd_s, o_gd_d,
        src_gg, dst_gg, o_gg_s, o_gg_d, E);

    norm_kernel<<<(nTot + 255) / 256, 256>>>(nTot);

    const int nScanBlk = (nScan + SCAN_BLK - 1) / SCAN_BLK;
    scan1<<<nScanBlk, 256>>>(nScan, nDrug, nGene, o_dd_d, o_gd_d, o_dg_d, o_gg_d);
    scan2<<<1, 512>>>(nScanBlk);
    scan3<<<(nScan + 255) / 256, 256>>>(nScan);

    bin_all<<<(int)((totDeg + 255) / 256), 256>>>(
        src_dd, dst_dd,
        src_gd, dst_gd,
        src_dg, dst_dg,
        src_gg, dst_gg, E, nDrug, nGene);

    // projection GEMMs: h = (nsrc ⊙ x) @ W, fp16 in/out, fp32 accum
    cudaFuncSetAttribute(gemm_h, cudaFuncAttributeMaxDynamicSharedMemorySize, GEMMH_SMEM);
    dim3 gD((nDrug + 127) / 128, 2), gG((nGene + 127) / 128, 2);
    gemm_h<<<gD, 512, GEMMH_SMEM>>>(x_drug, normP + o_dd_s, normP + o_dg_s,
                                    W_dd, W_dg, hD, nDrug);
    gemm_h<<<gG, 512, GEMMH_SMEM>>>(x_gene, normP + o_gd_s, normP + o_gg_s,
                                    W_gd, W_gg, hG, nGene);

    // final gather + epilogue: two warps per dst node, 4 nodes per block
    gather_out<<<(nDrug + nGene + 3) / 4, 256>>>(
        h_bias, out, nDrug, nGene, o_dd_d, o_gd_d, o_dg_d, o_gg_d);
}

// round 12
// speedup vs baseline: 2.6498x; 1.0465x over previous
#include <cuda_runtime.h>
#include <cuda_fp16.h>
#include <cstdint>
#include <math.h>
#include <mma.h>

using namespace nvcuda;

#define DIM 128

// ---------------- scratch (device globals; no allocation allowed) ----------------
__device__ int    g_deg [600000];
__device__ float  g_norm[600000];
__device__ int    g_base  [300000];   // CSR row starts: [dd | gd | dg | gg] (by dst)
__device__ int    g_cursor[300000];
__device__ int    g_bsum  [512];
__device__ int    g_ebuf  [2400000];  // binned src indices
__device__ __half g_hD[100000ull * 256];  // drug proj: cols 0-127 = dd, 128-255 = dg
__device__ __half g_hG[ 50000ull * 256];  // gene proj: cols 0-127 = gd, 128-255 = gg

// ---------------- zero deg ----------------
__global__ void zero_deg() {
    int i = blockIdx.x * blockDim.x + threadIdx.x;
    if (i < 600000 / 4) ((int4*)g_deg)[i] = make_int4(0, 0, 0, 0);
}

// ---------------- degree counting (all 4 etypes) ----------------
__global__ void deg_all(const int* __restrict__ s0, const int* __restrict__ d0, int o0s, int o0d,
                        const int* __restrict__ s1, const int* __restrict__ d1, int o1s, int o1d,
                        const int* __restrict__ s2, const int* __restrict__ d2, int o2s, int o2d,
                        const int* __restrict__ s3, const int* __restrict__ d3, int o3s, int o3d,
                        int E) {
    int i = blockIdx.x * blockDim.x + threadIdx.x;
    const int *s, *d; int os, od, j;
    if (i < E)          { s = s0; d = d0; os = o0s; od = o0d; j = i; }
    else if (i < 2 * E) { s = s1; d = d1; os = o1s; od = o1d; j = i - E; }
    else if (i < 3 * E) { s = s2; d = d2; os = o2s; od = o2d; j = i - 2 * E; }
    else if (i < 4 * E) { s = s3; d = d3; os = o3s; od = o3d; j = i - 3 * E; }
    else return;
    atomicAdd(&g_deg[os + __ldg(s + j)], 1);
    atomicAdd(&g_deg[od + __ldg(d + j)], 1);
}

__global__ void norm_kernel(int n) {
    int i = blockIdx.x * blockDim.x + threadIdx.x;
    if (i < n) g_norm[i] = rsqrtf(fmaxf((float)g_deg[i], 1.0f));
}

// ---------------- 3-phase exclusive scan over concatenated dst degrees ----------------
#define SCAN_BLK 1024
__global__ void scan1(int total, int nDrug, int nGene,
                      int o_dd_d, int o_gd_d, int o_dg_d, int o_gg_d) {
    __shared__ int sh[256];
    const int tid = threadIdx.x;
    const int base = blockIdx.x * SCAN_BLK + tid * 4;
    const int c1 = nDrug, c2 = 2 * nDrug, c3 = 2 * nDrug + nGene;
    int v[4], ssum = 0;
    #pragma unroll
    for (int q = 0; q < 4; q++) {
        int i = base + q, d = 0;
        if (i < total) {
            int idx;
            if (i < c1)      idx = o_dd_d + i;
            else if (i < c2) idx = o_gd_d + i - c1;
            else if (i < c3) idx = o_dg_d + i - c2;
            else             idx = o_gg_d + i - c3;
            d = g_deg[idx];
        }
        v[q] = d; ssum += d;
    }
    sh[tid] = ssum; __syncthreads();
    for (int off = 1; off < 256; off <<= 1) {
        int t = (tid >= off) ? sh[tid - off] : 0;
        __syncthreads();
        sh[tid] += t;
        __syncthreads();
    }
    int run = sh[tid] - ssum;
    if (tid == 255) g_bsum[blockIdx.x] = sh[255];
    #pragma unroll
    for (int q = 0; q < 4; q++) {
        int i = base + q;
        if (i < total) g_base[i] = run;
        run += v[q];
    }
}

__global__ void scan2(int n) {
    __shared__ int sh[512];
    int tid = threadIdx.x;
    int v = (tid < n) ? g_bsum[tid] : 0;
    sh[tid] = v; __syncthreads();
    for (int off = 1; off < 512; off <<= 1) {
        int t = (tid >= off) ? sh[tid - off] : 0;
        __syncthreads();
        sh[tid] += t;
        __syncthreads();
    }
    if (tid < n) g_bsum[tid] = sh[tid] - v;
}

__global__ void scan3(int total) {
    int i = blockIdx.x * blockDim.x + threadIdx.x;
    if (i < total) {
        int v = g_base[i] + g_bsum[i / SCAN_BLK];
        g_base[i] = v;
        g_cursor[i] = v;
    }
}

// ---------------- binning: ebuf[pos] = src (CSR by dst); segment order dd, gd, dg, gg ----------------
__global__ void bin_all(const int* __restrict__ s0, const int* __restrict__ d0,
                        const int* __restrict__ s1, const int* __restrict__ d1,
                        const int* __restrict__ s2, const int* __restrict__ d2,
                        const int* __restrict__ s3, const int* __restrict__ d3,
                        int E, int nDrug, int nGene) {
    int i = blockIdx.x * blockDim.x + threadIdx.x;
    const int *s, *d; int off, j;
    if (i < E)          { s = s0; d = d0; off = 0;                 j = i; }
    else if (i < 2 * E) { s = s1; d = d1; off = nDrug;             j = i - E; }
    else if (i < 3 * E) { s = s2; d = d2; off = 2 * nDrug;         j = i - 2 * E; }
    else if (i < 4 * E) { s = s3; d = d3; off = 2 * nDrug + nGene; j = i - 3 * E; }
    else return;
    int dd = __ldg(d + j);
    int pos = atomicAdd(&g_cursor[off + dd], 1);
    g_ebuf[pos] = __ldg(s + j);
}

// ---------------- projection GEMM (fp16 m16n16k16): h[:, yh*128:+128] = (nsrc ⊙ x) @ W ----------------
// 512 threads / 16 warps: warp -> 16 rows x 64 cols (4 tiles). 32 warps/SM at 2 CTAs.
#define HPAD 136
#define CPAD 136
#define GEMMH_SMEM (2 * 128 * HPAD * 2)     // 69632 B  (== 128*CPAD*4 overlay)

__global__ void __launch_bounds__(512, 2)
gemm_h(const float* __restrict__ x,
       const float* __restrict__ ns0, const float* __restrict__ ns1,
       const float* __restrict__ W0, const float* __restrict__ W1,
       __half* __restrict__ h, int M) {
    extern __shared__ char smraw[];
    __half* Bs = (__half*)smraw;                  // [128][HPAD]
    __half* As = (__half*)smraw + 128 * HPAD;     // [128][HPAD]
    float*  Cf = (float*)smraw;                   // [128][CPAD] (overlay after MMA)
    const int tid = threadIdx.x, wid = tid >> 5;
    const int yh = blockIdx.y;
    const float* W  = yh ? W1  : W0;
    const float* ns = yh ? ns1 : ns0;

    for (int i = tid; i < 128 * 32; i += 512) {
        int k = i >> 5, nq = i & 31;
        float4 v = __ldg((const float4*)(W + k * 128) + nq);
        __half2* p = (__half2*)&Bs[k * HPAD + nq * 4];
        p[0] = __floats2half2_rn(v.x, v.y);
        p[1] = __floats2half2_rn(v.z, v.w);
    }

    const int rowBase = blockIdx.x * 128;
    for (int i = tid; i < 4096; i += 512) {
        int m = i >> 5, kq = i & 31;
        int gr = rowBase + m;
        float4 v = make_float4(0.f, 0.f, 0.f, 0.f);
        if (gr < M) {
            v = __ldg((const float4*)(x + (size_t)gr * DIM) + kq);
            float s = __ldg(ns + gr);
            v.x *= s; v.y *= s; v.z *= s; v.w *= s;
        }
        __half2* p = (__half2*)&As[m * HPAD + kq * 4];
        p[0] = __floats2half2_rn(v.x, v.y);
        p[1] = __floats2half2_rn(v.z, v.w);
    }
    __syncthreads();

    const int wrow = (wid >> 1) * 16;
    const int wcol = (wid & 1) * 64;
    wmma::fragment<wmma::accumulator, 16, 16, 16, float> c[4];
    #pragma unroll
    for (int t = 0; t < 4; t++) wmma::fill_fragment(c[t], 0.0f);

    #pragma unroll
    for (int ks = 0; ks < 8; ks++) {
        wmma::fragment<wmma::matrix_a, 16, 16, 16, __half, wmma::row_major> a;
        wmma::load_matrix_sync(a, &As[wrow * HPAD + ks * 16], HPAD);
        #pragma unroll
        for (int t = 0; t < 4; t++) {
            wmma::fragment<wmma::matrix_b, 16, 16, 16, __half, wmma::row_major> b;
            wmma::load_matrix_sync(b, &Bs[(ks * 16) * HPAD + wcol + t * 16], HPAD);
            wmma::mma_sync(c[t], a, b, c[t]);
        }
    }
    __syncthreads();

    float* Cw = Cf + wrow * CPAD + wcol;
    #pragma unroll
    for (int t = 0; t < 4; t++)
        wmma::store_matrix_sync(&Cw[t * 16], c[t], CPAD, wmma::mem_row_major);
    __syncthreads();

    for (int i = tid; i < 128 * 64; i += 512) {
        int m = i >> 6, c2 = i & 63;
        int gr = rowBase + m;
        if (gr < M) {
            const float* p = &Cf[m * CPAD + c2 * 2];
            __half2* hp = (__half2*)(h + (size_t)gr * 256 + yh * 128);
            hp[c2] = __floats2half2_rn(p[0], p[1]);
        }
    }
}

// ---------------- final gather: TWO warps per dst node (one per etype list) ----------------
__global__ void __launch_bounds__(256)
gather_out(const float* __restrict__ bias, float* __restrict__ out,
           int nDrug, int nGene,
           int o_dd_d, int o_gd_d, int o_dg_d, int o_gg_d) {
    __shared__ float4 red[8][32];
    const int tid  = threadIdx.x;
    const int wid  = tid >> 5, lane = tid & 31;
    const int node = blockIdx.x * 4 + (wid >> 1);
    const int list = wid & 1;
    const int nNodes = nDrug + nGene;

    float4 acc = make_float4(0.f, 0.f, 0.f, 0.f);
    float nn = 0.f;

    if (node < nNodes) {
        const __half* h; int colOff, b, dg, odst;
        if (node < nDrug) {
            int r = node; colOff = 0;
            if (list == 0) { h = g_hD; b = __ldg(g_base + r);         odst = o_dd_d; }
            else           { h = g_hG; b = __ldg(g_base + nDrug + r); odst = o_gd_d; }
            dg = __ldg(g_deg + odst + r); nn = __ldg(g_norm + odst + r);
        } else {
            int r = node - nDrug; colOff = 128;
            if (list == 0) { h = g_hD; b = __ldg(g_base + 2 * nDrug + r);         odst = o_dg_d; }
            else           { h = g_hG; b = __ldg(g_base + 2 * nDrug + nGene + r); odst = o_gg_d; }
            dg = __ldg(g_deg + odst + r); nn = __ldg(g_norm + odst + r);
        }

        const uint2* hp = (const uint2*)(h + colOff);
        int j = b; const int e = b + dg;
        for (; j + 8 <= e; j += 8) {
            int s[8];
            #pragma unroll
            for (int q = 0; q < 8; q++) s[q] = __ldg(g_ebuf + j + q);
            uint2 u[8];
            #pragma unroll
            for (int q = 0; q < 8; q++) u[q] = __ldg(hp + (size_t)s[q] * 64 + lane);
            #pragma unroll
            for (int q = 0; q < 8; q++) {
                float2 a = __half22float2(*(const __half2*)&u[q].x);
                float2 c = __half22float2(*(const __half2*)&u[q].y);
                acc.x += a.x; acc.y += a.y; acc.z += c.x; acc.w += c.y;
            }
        }
        for (; j + 2 <= e; j += 2) {
            int s0 = __ldg(g_ebuf + j), s1 = __ldg(g_ebuf + j + 1);
            uint2 u0 = __ldg(hp + (size_t)s0 * 64 + lane);
            uint2 u1 = __ldg(hp + (size_t)s1 * 64 + lane);
            float2 a0 = __half22float2(*(const __half2*)&u0.x);
            float2 c0 = __half22float2(*(const __half2*)&u0.y);
            float2 a1 = __half22float2(*(const __half2*)&u1.x);
            float2 c1 = __half22float2(*(const __half2*)&u1.y);
            acc.x += a0.x + a1.x; acc.y += a0.y + a1.y;
            acc.z += c0.x + c1.x; acc.w += c0.y + c1.y;
        }
        if (j < e) {
            int s = __ldg(g_ebuf + j);
            uint2 u = __ldg(hp + (size_t)s * 64 + lane);
            float2 a = __half22float2(*(const __half2*)&u.x);
            float2 c = __half22float2(*(const __half2*)&u.y);
            acc.x += a.x; acc.y += a.y; acc.z += c.x; acc.w += c.y;
        }
    }
    acc.x *= nn; acc.y *= nn; acc.z *= nn; acc.w *= nn;
    red[wid][lane] = acc;
    __syncthreads();

    if (list == 0 && node < nNodes) {
        float4 o = red[wid + 1][lane];
        float4 bb = __ldg((const float4*)bias + lane);
        float4 v;
        v.x = fmaxf(acc.x + o.x + bb.x, 0.f);
        v.y = fmaxf(acc.y + o.y + bb.y, 0.f);
        v.z = fmaxf(acc.z + o.z + bb.z, 0.f);
        v.w = fmaxf(acc.w + o.w + bb.w, 0.f);

        float ss = v.x * v.x + v.y * v.y + v.z * v.z + v.w * v.w;
        #pragma unroll
        for (int off = 16; off > 0; off >>= 1)
            ss += __shfl_xor_sync(0xffffffffu, ss, off);
        float inv = 1.0f / fmaxf(sqrtf(ss), 1e-12f);
        v.x *= inv; v.y *= inv; v.z *= inv; v.w *= inv;

        *((float4*)(out + (size_t)node * DIM) + lane) = v;
    }
}

// ---------------- launch (fork/join overlap: {scan,bin} || {gemm}) ----------------
extern "C" void kernel_launch(void* const* d_in, const int* in_sizes, int n_in,
                              void* d_out, int out_size) {
    const float* x_drug = (const float*)d_in[0];
    const float* x_gene = (const float*)d_in[1];
    const float* W_dd   = (const float*)d_in[2];
    const float* W_dg   = (const float*)d_in[3];
    const float* W_gd   = (const float*)d_in[4];
    const float* W_gg   = (const float*)d_in[5];
    const float* h_bias = (const float*)d_in[6];
    const int* src_dd = (const int*)d_in[7];   const int* dst_dd = (const int*)d_in[8];
    const int* src_dg = (const int*)d_in[9];   const int* dst_dg = (const int*)d_in[10];
    const int* src_gd = (const int*)d_in[11];  const int* dst_gd = (const int*)d_in[12];
    const int* src_gg = (const int*)d_in[13];  const int* dst_gg = (const int*)d_in[14];
    float* out = (float*)d_out;

    const int E     = in_sizes[7];
    const int nDrug = in_sizes[0] / DIM;
    const int nGene = in_sizes[1] / DIM;

    const int o_dd_s = 0;
    const int o_dd_d = o_dd_s + nDrug;
    const int o_dg_s = o_dd_d + nDrug;
    const int o_dg_d = o_dg_s + nDrug;
    const int o_gd_s = o_dg_d + nGene;
    const int o_gd_d = o_gd_s + nGene;
    const int o_gg_s = o_gd_d + nDrug;
    const int o_gg_d = o_gg_s + nGene;
    const int nTot   = o_gg_d + nGene;          // 600000
    const int nScan  = 2 * nDrug + 2 * nGene;   // 300000

    float* normP;
    __half *hD, *hG;
    cudaGetSymbolAddress((void**)&normP, g_norm);
    cudaGetSymbolAddress((void**)&hD, g_hD);
    cudaGetSymbolAddress((void**)&hG, g_hG);

    // lazily-created side stream + fork/join events (resource handles only;
    // per-call work is identical and fully ordered by the events)
    static cudaStream_t sSide = nullptr;
    static cudaEvent_t evFork = nullptr, evJoin = nullptr;
    if (sSide == nullptr) {
        cudaStreamCreateWithFlags(&sSide, cudaStreamNonBlocking);
        cudaEventCreateWithFlags(&evFork, cudaEventDisableTiming);
        cudaEventCreateWithFlags(&evJoin, cudaEventDisableTiming);
    }

    zero_deg<<<(600000 / 4 + 255) / 256, 256>>>();

    const long long totDeg = 4LL * E;
    deg_all<<<(int)((totDeg + 255) / 256), 256>>>(
        src_dd, dst_dd, o_dd_s, o_dd_d,
        src_dg, dst_dg, o_dg_s, o_dg_d,
        src_gd, dst_gd, o_gd_s, o_gd_d,
        src_gg, dst_gg, o_gg_s, o_gg_d, E);

    norm_kernel<<<(nTot + 255) / 256, 256>>>(nTot);

    // fork: gemm chain on side stream (depends only on norms)
    cudaEventRecord(evFork, 0);
    cudaStreamWaitEvent(sSide, evFork, 0);

    cudaFuncSetAttribute(gemm_h, cudaFuncAttributeMaxDynamicSharedMemorySize, GEMMH_SMEM);
    dim3 gD((nDrug + 127) / 128, 2), gG((nGene + 127) / 128, 2);
    gemm_h<<<gD, 512, GEMMH_SMEM, sSide>>>(x_drug, normP + o_dd_s, normP + o_dg_s,
                                           W_dd, W_dg, hD, nDrug);
    gemm_h<<<gG, 512, GEMMH_SMEM, sSide>>>(x_gene, normP + o_gd_s, normP + o_gg_s,
                                           W_gd, W_gg, hG, nGene);
    cudaEventRecord(evJoin, sSide);

    // main stream: scan + bin (independent of gemm)
    const int nScanBlk = (nScan + SCAN_BLK - 1) / SCAN_BLK;
    scan1<<<nScanBlk, 256>>>(nScan, nDrug, nGene, o_dd_d, o_gd_d, o_dg_d, o_gg_d);
    scan2<<<1, 512>>>(nScanBlk);
    scan3<<<(nScan + 255) / 256, 256>>>(nScan);

    bin_all<<<(int)((totDeg + 255) / 256), 256>>>(
        src_dd, dst_dd,
        src_gd, dst_gd,
        src_dg, dst_dg,
        src_gg, dst_gg, E, nDrug, nGene);

    // join: gather needs both bin (ebuf) and gemm (h)
    cudaStreamWaitEvent(0, evJoin, 0);
    gather_out<<<(nDrug + nGene + 3) / 4, 256>>>(
        h_bias, out, nDrug, nGene, o_dd_d, o_gd_d, o_dg_d, o_gg_d);
}

// round 13
// speedup vs baseline: 2.8536x; 1.0769x over previous
#include <cuda_runtime.h>
#include <cuda_fp16.h>
#include <cstdint>
#include <math.h>
#include <mma.h>

using namespace nvcuda;

#define DIM 128

// ---------------- scratch (device globals; no allocation allowed) ----------------
__device__ int    g_deg [600000];
__device__ float  g_norm[600000];
__device__ int    g_base  [300000];   // CSR row starts: [dd | gd | dg | gg] (by dst)
__device__ int    g_cursor[300000];
__device__ int    g_bsum  [512];
__device__ int    g_ebuf  [2400000];  // binned src indices
__device__ __half g_hD[100000ull * 256];  // drug proj: cols 0-127 = dd, 128-255 = dg
__device__ __half g_hG[ 50000ull * 256];  // gene proj: cols 0-127 = gd, 128-255 = gg

// ---------------- zero deg ----------------
__global__ void zero_deg() {
    int i = blockIdx.x * blockDim.x + threadIdx.x;
    if (i < 600000 / 4) ((int4*)g_deg)[i] = make_int4(0, 0, 0, 0);
}

// ---------------- degree counting (all 4 etypes) ----------------
__global__ void deg_all(const int* __restrict__ s0, const int* __restrict__ d0, int o0s, int o0d,
                        const int* __restrict__ s1, const int* __restrict__ d1, int o1s, int o1d,
                        const int* __restrict__ s2, const int* __restrict__ d2, int o2s, int o2d,
                        const int* __restrict__ s3, const int* __restrict__ d3, int o3s, int o3d,
                        int E) {
    int i = blockIdx.x * blockDim.x + threadIdx.x;
    const int *s, *d; int os, od, j;
    if (i < E)          { s = s0; d = d0; os = o0s; od = o0d; j = i; }
    else if (i < 2 * E) { s = s1; d = d1; os = o1s; od = o1d; j = i - E; }
    else if (i < 3 * E) { s = s2; d = d2; os = o2s; od = o2d; j = i - 2 * E; }
    else if (i < 4 * E) { s = s3; d = d3; os = o3s; od = o3d; j = i - 3 * E; }
    else return;
    atomicAdd(&g_deg[os + __ldg(s + j)], 1);
    atomicAdd(&g_deg[od + __ldg(d + j)], 1);
}

__global__ void norm_kernel(int n) {
    int i = blockIdx.x * blockDim.x + threadIdx.x;
    if (i < n) g_norm[i] = rsqrtf(fmaxf((float)g_deg[i], 1.0f));
}

// ---------------- 3-phase exclusive scan over concatenated dst degrees ----------------
#define SCAN_BLK 1024
__global__ void scan1(int total, int nDrug, int nGene,
                      int o_dd_d, int o_gd_d, int o_dg_d, int o_gg_d) {
    __shared__ int sh[256];
    const int tid = threadIdx.x;
    const int base = blockIdx.x * SCAN_BLK + tid * 4;
    const int c1 = nDrug, c2 = 2 * nDrug, c3 = 2 * nDrug + nGene;
    int v[4], ssum = 0;
    #pragma unroll
    for (int q = 0; q < 4; q++) {
        int i = base + q, d = 0;
        if (i < total) {
            int idx;
            if (i < c1)      idx = o_dd_d + i;
            else if (i < c2) idx = o_gd_d + i - c1;
            else if (i < c3) idx = o_dg_d + i - c2;
            else             idx = o_gg_d + i - c3;
            d = g_deg[idx];
        }
        v[q] = d; ssum += d;
    }
    sh[tid] = ssum; __syncthreads();
    for (int off = 1; off < 256; off <<= 1) {
        int t = (tid >= off) ? sh[tid - off] : 0;
        __syncthreads();
        sh[tid] += t;
        __syncthreads();
    }
    int run = sh[tid] - ssum;
    if (tid == 255) g_bsum[blockIdx.x] = sh[255];
    #pragma unroll
    for (int q = 0; q < 4; q++) {
        int i = base + q;
        if (i < total) g_base[i] = run;
        run += v[q];
    }
}

__global__ void scan2(int n) {
    __shared__ int sh[512];
    int tid = threadIdx.x;
    int v = (tid < n) ? g_bsum[tid] : 0;
    sh[tid] = v; __syncthreads();
    for (int off = 1; off < 512; off <<= 1) {
        int t = (tid >= off) ? sh[tid - off] : 0;
        __syncthreads();
        sh[tid] += t;
        __syncthreads();
    }
    if (tid < n) g_bsum[tid] = sh[tid] - v;
}

__global__ void scan3(int total) {
    int i = blockIdx.x * blockDim.x + threadIdx.x;
    if (i < total) {
        int v = g_base[i] + g_bsum[i / SCAN_BLK];
        g_base[i] = v;
        g_cursor[i] = v;
    }
}

// ---------------- binning: ebuf[pos] = src (CSR by dst); segment order dd, gd, dg, gg ----------------
__global__ void bin_all(const int* __restrict__ s0, const int* __restrict__ d0,
                        const int* __restrict__ s1, const int* __restrict__ d1,
                        const int* __restrict__ s2, const int* __restrict__ d2,
                        const int* __restrict__ s3, const int* __restrict__ d3,
                        int E, int nDrug, int nGene) {
    int i = blockIdx.x * blockDim.x + threadIdx.x;
    const int *s, *d; int off, j;
    if (i < E)          { s = s0; d = d0; off = 0;                 j = i; }
    else if (i < 2 * E) { s = s1; d = d1; off = nDrug;             j = i - E; }
    else if (i < 3 * E) { s = s2; d = d2; off = 2 * nDrug;         j = i - 2 * E; }
    else if (i < 4 * E) { s = s3; d = d3; off = 2 * nDrug + nGene; j = i - 3 * E; }
    else return;
    int dd = __ldg(d + j);
    int pos = atomicAdd(&g_cursor[off + dd], 1);
    g_ebuf[pos] = __ldg(s + j);
}

// ---------------- projection GEMM (fp16 m16n16k16), A shared across both yh ----------------
// h[:, yh*128:+128] = diag(ns_yh) * (x @ W_yh)   (ns applied in epilogue, fp32)
// 512 threads / 16 warps; warp -> 16 rows x 64 cols (4 tiles). 2 CTAs/SM.
// smem: As half[128][136] (kept) | Bs half[128][136]  overlaid by  Cf float[64][136]
#define HPAD 136
#define CPAD 136
#define GEMMH_SMEM (2 * 128 * HPAD * 2)     // 69632 B

__global__ void __launch_bounds__(512, 2)
gemm_all(const float* __restrict__ xD, const float* __restrict__ xG,
         const float* __restrict__ nsDD, const float* __restrict__ nsDG,
         const float* __restrict__ nsGD, const float* __restrict__ nsGG,
         const float* __restrict__ W_dd, const float* __restrict__ W_dg,
         const float* __restrict__ W_gd, const float* __restrict__ W_gg,
         __half* __restrict__ hD, __half* __restrict__ hG,
         int nDrug, int nGene, int nBlkD) {
    extern __shared__ char smraw[];
    __half* As = (__half*)smraw;                   // [128][HPAD] (lives across both yh)
    __half* Bs = (__half*)smraw + 128 * HPAD;      // [128][HPAD]
    float*  Cf = (float*)(smraw + 128 * HPAD * 2); // [64][CPAD] overlays Bs
    const int tid = threadIdx.x, wid = tid >> 5;

    const bool isD = blockIdx.x < nBlkD;
    const int bx = isD ? blockIdx.x : blockIdx.x - nBlkD;
    const float* x = isD ? xD : xG;
    const int    M = isD ? nDrug : nGene;
    __half*      h = isD ? hD : hG;
    const int rowBase = bx * 128;

    // Stage A = x rows (UNSCALED) -> half, once for both yh.
    for (int i = tid; i < 4096; i += 512) {
        int m = i >> 5, kq = i & 31;
        int gr = rowBase + m;
        float4 v = make_float4(0.f, 0.f, 0.f, 0.f);
        if (gr < M) v = __ldg((const float4*)(x + (size_t)gr * DIM) + kq);
        __half2* p = (__half2*)&As[m * HPAD + kq * 4];
        p[0] = __floats2half2_rn(v.x, v.y);
        p[1] = __floats2half2_rn(v.z, v.w);
    }

    const int wrow = (wid >> 1) * 16;      // 8 row groups
    const int wcol = (wid & 1) * 64;       // 2 col halves

    #pragma unroll
    for (int yh = 0; yh < 2; yh++) {
        const float* W  = isD ? (yh ? W_dg : W_dd) : (yh ? W_gg : W_gd);
        const float* ns = isD ? (yh ? nsDG : nsDD) : (yh ? nsGG : nsGD);

        // Stage B(yh). Bs region free here: yh=0 nothing yet; yh=1 the trailing
        // sync below guarantees prior epilogue finished reading Cf (overlay).
        for (int i = tid; i < 128 * 32; i += 512) {
            int k = i >> 5, nq = i & 31;
            float4 v = __ldg((const float4*)(W + k * 128) + nq);
            __half2* p = (__half2*)&Bs[k * HPAD + nq * 4];
            p[0] = __floats2half2_rn(v.x, v.y);
            p[1] = __floats2half2_rn(v.z, v.w);
        }
        __syncthreads();   // A (first iter) + B staged

        wmma::fragment<wmma::accumulator, 16, 16, 16, float> c[4];
        #pragma unroll
        for (int t = 0; t < 4; t++) wmma::fill_fragment(c[t], 0.0f);
        #pragma unroll
        for (int ks = 0; ks < 8; ks++) {
            wmma::fragment<wmma::matrix_a, 16, 16, 16, __half, wmma::row_major> a;
            wmma::load_matrix_sync(a, &As[wrow * HPAD + ks * 16], HPAD);
            #pragma unroll
            for (int t = 0; t < 4; t++) {
                wmma::fragment<wmma::matrix_b, 16, 16, 16, __half, wmma::row_major> b;
                wmma::load_matrix_sync(b, &Bs[(ks * 16) * HPAD + wcol + t * 16], HPAD);
                wmma::mma_sync(c[t], a, b, c[t]);
            }
        }

        // Epilogue in 2 phases of 64 rows; ns row-scaling applied in fp32.
        #pragma unroll
        for (int phase = 0; phase < 2; phase++) {
            __syncthreads();   // phase0: MMA done (Bs consumed); phase1: prev h-writes done
            if ((wid >> 3) == phase) {
                float* Cw = Cf + (wrow & 63) * CPAD + wcol;
                #pragma unroll
                for (int t = 0; t < 4; t++)
                    wmma::store_matrix_sync(&Cw[t * 16], c[t], CPAD, wmma::mem_row_major);
            }
            __syncthreads();
            for (int i = tid; i < 64 * 64; i += 512) {
                int m = i >> 6, c2 = i & 63;
                int gr = rowBase + phase * 64 + m;
                if (gr < M) {
                    float s = __ldg(ns + gr);
                    const float* p = &Cf[m * CPAD + c2 * 2];
                    __half2* hp = (__half2*)(h + (size_t)gr * 256 + yh * 128);
                    hp[c2] = __floats2half2_rn(p[0] * s, p[1] * s);
                }
            }
        }
        __syncthreads();   // phase-1 h-writes done before Bs restage (Cf overlay)
    }
}

// ---------------- final gather: TWO warps per dst node (one per etype list) ----------------
__global__ void __launch_bounds__(256)
gather_out(const float* __restrict__ bias, float* __restrict__ out,
           int nDrug, int nGene,
           int o_dd_d, int o_gd_d, int o_dg_d, int o_gg_d) {
    __shared__ float4 red[8][32];
    const int tid  = threadIdx.x;
    const int wid  = tid >> 5, lane = tid & 31;
    const int node = blockIdx.x * 4 + (wid >> 1);
    const int list = wid & 1;
    const int nNodes = nDrug + nGene;

    float4 acc = make_float4(0.f, 0.f, 0.f, 0.f);
    float nn = 0.f;

    if (node < nNodes) {
        const __half* h; int colOff, b, dg, odst;
        if (node < nDrug) {
            int r = node; colOff = 0;
            if (list == 0) { h = g_hD; b = __ldg(g_base + r);         odst = o_dd_d; }
            else           { h = g_hG; b = __ldg(g_base + nDrug + r); odst = o_gd_d; }
            dg = __ldg(g_deg + odst + r); nn = __ldg(g_norm + odst + r);
        } else {
            int r = node - nDrug; colOff = 128;
            if (list == 0) { h = g_hD; b = __ldg(g_base + 2 * nDrug + r);         odst = o_dg_d; }
            else           { h = g_hG; b = __ldg(g_base + 2 * nDrug + nGene + r); odst = o_gg_d; }
            dg = __ldg(g_deg + odst + r); nn = __ldg(g_norm + odst + r);
        }

        const uint2* hp = (const uint2*)(h + colOff);
        int j = b; const int e = b + dg;
        for (; j + 8 <= e; j += 8) {
            int s[8];
            #pragma unroll
            for (int q = 0; q < 8; q++) s[q] = __ldg(g_ebuf + j + q);
            uint2 u[8];
            #pragma unroll
            for (int q = 0; q < 8; q++) u[q] = __ldg(hp + (size_t)s[q] * 64 + lane);
            #pragma unroll
            for (int q = 0; q < 8; q++) {
                float2 a = __half22float2(*(const __half2*)&u[q].x);
                float2 c = __half22float2(*(const __half2*)&u[q].y);
                acc.x += a.x; acc.y += a.y; acc.z += c.x; acc.w += c.y;
            }
        }
        for (; j + 2 <= e; j += 2) {
            int s0 = __ldg(g_ebuf + j), s1 = __ldg(g_ebuf + j + 1);
            uint2 u0 = __ldg(hp + (size_t)s0 * 64 + lane);
            uint2 u1 = __ldg(hp + (size_t)s1 * 64 + lane);
            float2 a0 = __half22float2(*(const __half2*)&u0.x);
            float2 c0 = __half22float2(*(const __half2*)&u0.y);
            float2 a1 = __half22float2(*(const __half2*)&u1.x);
            float2 c1 = __half22float2(*(const __half2*)&u1.y);
            acc.x += a0.x + a1.x; acc.y += a0.y + a1.y;
            acc.z += c0.x + c1.x; acc.w += c0.y + c1.y;
        }
        if (j < e) {
            int s = __ldg(g_ebuf + j);
            uint2 u = __ldg(hp + (size_t)s * 64 + lane);
            float2 a = __half22float2(*(const __half2*)&u.x);
            float2 c = __half22float2(*(const __half2*)&u.y);
            acc.x += a.x; acc.y += a.y; acc.z += c.x; acc.w += c.y;
        }
    }
    acc.x *= nn; acc.y *= nn; acc.z *= nn; acc.w *= nn;
    red[wid][lane] = acc;
    __syncthreads();

    if (list == 0 && node < nNodes) {
        float4 o = red[wid + 1][lane];
        float4 bb = __ldg((const float4*)bias + lane);
        float4 v;
        v.x = fmaxf(acc.x + o.x + bb.x, 0.f);
        v.y = fmaxf(acc.y + o.y + bb.y, 0.f);
        v.z = fmaxf(acc.z + o.z + bb.z, 0.f);
        v.w = fmaxf(acc.w + o.w + bb.w, 0.f);

        float ss = v.x * v.x + v.y * v.y + v.z * v.z + v.w * v.w;
        #pragma unroll
        for (int off = 16; off > 0; off >>= 1)
            ss += __shfl_xor_sync(0xffffffffu, ss, off);
        float inv = 1.0f / fmaxf(sqrtf(ss), 1e-12f);
        v.x *= inv; v.y *= inv; v.z *= inv; v.w *= inv;

        *((float4*)(out + (size_t)node * DIM) + lane) = v;
    }
}

// ---------------- launch (fork/join overlap: {scan,bin} || {gemm}) ----------------
extern "C" void kernel_launch(void* const* d_in, const int* in_sizes, int n_in,
                              void* d_out, int out_size) {
    const float* x_drug = (const float*)d_in[0];
    const float* x_gene = (const float*)d_in[1];
    const float* W_dd   = (const float*)d_in[2];
    const float* W_dg   = (const float*)d_in[3];
    const float* W_gd   = (const float*)d_in[4];
    const float* W_gg   = (const float*)d_in[5];
    const float* h_bias = (const float*)d_in[6];
    const int* src_dd = (const int*)d_in[7];   const int* dst_dd = (const int*)d_in[8];
    const int* src_dg = (const int*)d_in[9];   const int* dst_dg = (const int*)d_in[10];
    const int* src_gd = (const int*)d_in[11];  const int* dst_gd = (const int*)d_in[12];
    const int* src_gg = (const int*)d_in[13];  const int* dst_gg = (const int*)d_in[14];
    float* out = (float*)d_out;

    const int E     = in_sizes[7];
    const int nDrug = in_sizes[0] / DIM;
    const int nGene = in_sizes[1] / DIM;

    const int o_dd_s = 0;
    const int o_dd_d = o_dd_s + nDrug;
    const int o_dg_s = o_dd_d + nDrug;
    const int o_dg_d = o_dg_s + nDrug;
    const int o_gd_s = o_dg_d + nGene;
    const int o_gd_d = o_gd_s + nGene;
    const int o_gg_s = o_gd_d + nDrug;
    const int o_gg_d = o_gg_s + nGene;
    const int nTot   = o_gg_d + nGene;          // 600000
    const int nScan  = 2 * nDrug + 2 * nGene;   // 300000

    float* normP;
    __half *hD, *hG;
    cudaGetSymbolAddress((void**)&normP, g_norm);
    cudaGetSymbolAddress((void**)&hD, g_hD);
    cudaGetSymbolAddress((void**)&hG, g_hG);

    static cudaStream_t sSide = nullptr;
    static cudaEvent_t evFork = nullptr, evJoin = nullptr;
    if (sSide == nullptr) {
        cudaStreamCreateWithFlags(&sSide, cudaStreamNonBlocking);
        cudaEventCreateWithFlags(&evFork, cudaEventDisableTiming);
        cudaEventCreateWithFlags(&evJoin, cudaEventDisableTiming);
    }

    zero_deg<<<(600000 / 4 + 255) / 256, 256>>>();

    const long long totDeg = 4LL * E;
    deg_all<<<(int)((totDeg + 255) / 256), 256>>>(
        src_dd, dst_dd, o_dd_s, o_dd_d,
        src_dg, dst_dg, o_dg_s, o_dg_d,
        src_gd, dst_gd, o_gd_s, o_gd_d,
        src_gg, dst_gg, o_gg_s, o_gg_d, E);

    norm_kernel<<<(nTot + 255) / 256, 256>>>(nTot);

    // fork: gemm on side stream (depends only on norms)
    cudaEventRecord(evFork, 0);
    cudaStreamWaitEvent(sSide, evFork, 0);

    cudaFuncSetAttribute(gemm_all, cudaFuncAttributeMaxDynamicSharedMemorySize, GEMMH_SMEM);
    const int nBlkD = (nDrug + 127) / 128;
    const int nBlkG = (nGene + 127) / 128;
    gemm_all<<<nBlkD + nBlkG, 512, GEMMH_SMEM, sSide>>>(
        x_drug, x_gene,
        normP + o_dd_s, normP + o_dg_s, normP + o_gd_s, normP + o_gg_s,
        W_dd, W_dg, W_gd, W_gg, hD, hG, nDrug, nGene, nBlkD);
    cudaEventRecord(evJoin, sSide);

    // main stream: scan + bin (independent of gemm)
    const int nScanBlk = (nScan + SCAN_BLK - 1) / SCAN_BLK;
    scan1<<<nScanBlk, 256>>>(nScan, nDrug, nGene, o_dd_d, o_gd_d, o_dg_d, o_gg_d);
    scan2<<<1, 512>>>(nScanBlk);
    scan3<<<(nScan + 255) / 256, 256>>>(nScan);

    bin_all<<<(int)((totDeg + 255) / 256), 256>>>(
        src_dd, dst_dd,
        src_gd, dst_gd,
        src_dg, dst_dg,
        src_gg, dst_gg, E, nDrug, nGene);

    // join: gather needs both bin (ebuf) and gemm (h)
    cudaStreamWaitEvent(0, evJoin, 0);
    gather_out<<<(nDrug + nGene + 3) / 4, 256>>>(
        h_bias, out, nDrug, nGene, o_dd_d, o_gd_d, o_dg_d, o_gg_d);
}